// round 2
// baseline (speedup 1.0000x reference)
#include <cuda_runtime.h>

#define TILE_R    32
#define THREADS   256
#define NODE_DIM  128
#define EDGE_DIM  64
#define IN_DIM    192
#define OUT_DIM   128
#define XS_STRIDE 200   // 192 + 8 pad
#define AS_STRIDE 132   // 128 + 4 pad

// ---- packed f32x2 helpers (FFMA2 — only reachable via PTX) ----
__device__ __forceinline__ unsigned long long pack_dup(float v) {
    unsigned long long r;
    asm("mov.b64 %0, {%1, %1};" : "=l"(r) : "f"(v));
    return r;
}
__device__ __forceinline__ void ffma2(unsigned long long &d, unsigned long long a, unsigned long long b) {
    asm("fma.rn.f32x2 %0, %1, %2, %0;" : "+l"(d) : "l"(a), "l"(b));
}
__device__ __forceinline__ float2 unpack2(unsigned long long v) {
    float lo, hi;
    asm("mov.b64 {%0, %1}, %2;" : "=f"(lo), "=f"(hi) : "l"(v));
    return make_float2(lo, hi);
}

__device__ __forceinline__ float silu_f(float g) {
    return g / (1.0f + __expf(-g));
}

__global__ __launch_bounds__(THREADS, 1)
void edge_mlp_kernel(const float* __restrict__ src,
                     const float* __restrict__ edg,
                     const float* __restrict__ W1,
                     const float* __restrict__ b1,
                     const float* __restrict__ gamma,
                     const float* __restrict__ beta,
                     const float* __restrict__ W2,
                     const float* __restrict__ b2,
                     float* __restrict__ out,
                     int nrows)
{
    extern __shared__ float smem[];
    float* W1s = smem;                                   // 192*128
    float* W2s = W1s + IN_DIM * OUT_DIM;                 // 128*128
    float* xs  = W2s + OUT_DIM * OUT_DIM;                // 32*200
    float* hs  = xs  + TILE_R * XS_STRIDE;               // 32*132
    float* b1s = hs  + TILE_R * AS_STRIDE;
    float* b2s = b1s + OUT_DIM;
    float* gs  = b2s + OUT_DIM;
    float* bes = gs  + OUT_DIM;

    const int tid = threadIdx.x;

    // One-time weight load into SMEM (persistent CTA)
    for (int i = tid; i < IN_DIM * OUT_DIM / 4; i += THREADS)
        ((float4*)W1s)[i] = ((const float4*)W1)[i];
    for (int i = tid; i < OUT_DIM * OUT_DIM / 4; i += THREADS)
        ((float4*)W2s)[i] = ((const float4*)W2)[i];
    if (tid < OUT_DIM) {
        b1s[tid] = b1[tid];
        b2s[tid] = b2[tid];
        gs[tid]  = gamma[tid];
        bes[tid] = beta[tid];
    }
    __syncthreads();

    const int tc  = tid & 31;         // col group: cols [4tc, 4tc+3]
    const int trr = (tid >> 5) << 2;  // local row base: rows [trr, trr+3]
    const int ntiles = nrows / TILE_R;

    const float4 b1v = *(const float4*)&b1s[tc * 4];
    const float4 b2v = *(const float4*)&b2s[tc * 4];
    const float4 gv  = *(const float4*)&gs[tc * 4];
    const float4 bev = *(const float4*)&bes[tc * 4];

    for (int tile = blockIdx.x; tile < ntiles; tile += gridDim.x) {
        const int rowbase = tile * TILE_R;

        // ---- stage x tile (32 x 192) into SMEM, coalesced float4 ----
        #pragma unroll
        for (int it = 0; it < (TILE_R * IN_DIM / 4) / THREADS; ++it) {   // 6 iters
            int c   = it * THREADS + tid;            // 0..1535
            int row = c / (IN_DIM / 4);              // /48
            int kg  = c - row * (IN_DIM / 4);        // 0..47
            float4 v;
            if (kg < NODE_DIM / 4)
                v = ((const float4*)(src + (long)(rowbase + row) * NODE_DIM))[kg];
            else
                v = ((const float4*)(edg + (long)(rowbase + row) * EDGE_DIM))[kg - NODE_DIM / 4];
            *(float4*)&xs[row * XS_STRIDE + kg * 4] = v;
        }
        __syncthreads();

        // ---- GEMM1: h[r][c] = x[r] . W1[:,c], 4x4 micro-tile, FFMA2 ----
        unsigned long long acc[4][2];
        #pragma unroll
        for (int r = 0; r < 4; ++r) { acc[r][0] = 0ull; acc[r][1] = 0ull; }

        const float* x0 = &xs[(trr + 0) * XS_STRIDE];
        const float* x1 = &xs[(trr + 1) * XS_STRIDE];
        const float* x2 = &xs[(trr + 2) * XS_STRIDE];
        const float* x3 = &xs[(trr + 3) * XS_STRIDE];
        const float* wp = &W1s[tc * 4];

        #pragma unroll 8
        for (int k = 0; k < IN_DIM; ++k) {
            ulonglong2 w = *(const ulonglong2*)(wp + k * OUT_DIM);  // W[k][4tc..4tc+3]
            unsigned long long xx0 = pack_dup(x0[k]);
            unsigned long long xx1 = pack_dup(x1[k]);
            unsigned long long xx2 = pack_dup(x2[k]);
            unsigned long long xx3 = pack_dup(x3[k]);
            ffma2(acc[0][0], w.x, xx0); ffma2(acc[0][1], w.y, xx0);
            ffma2(acc[1][0], w.x, xx1); ffma2(acc[1][1], w.y, xx1);
            ffma2(acc[2][0], w.x, xx2); ffma2(acc[2][1], w.y, xx2);
            ffma2(acc[3][0], w.x, xx3); ffma2(acc[3][1], w.y, xx3);
        }

        // ---- +bias, LayerNorm (warp reduce over 128 cols), SiLU -> hs ----
        #pragma unroll
        for (int r = 0; r < 4; ++r) {
            float2 a01 = unpack2(acc[r][0]);
            float2 a23 = unpack2(acc[r][1]);
            float h0 = a01.x + b1v.x, h1 = a01.y + b1v.y;
            float h2 = a23.x + b1v.z, h3 = a23.y + b1v.w;
            float s = h0 + h1 + h2 + h3;
            float q = h0 * h0 + h1 * h1 + h2 * h2 + h3 * h3;
            #pragma unroll
            for (int o = 16; o > 0; o >>= 1) {
                s += __shfl_xor_sync(0xffffffffu, s, o);
                q += __shfl_xor_sync(0xffffffffu, q, o);
            }
            float mu  = s * (1.0f / 128.0f);
            float var = q * (1.0f / 128.0f) - mu * mu;
            float inv = rsqrtf(var + 1e-5f);
            float g0 = (h0 - mu) * inv * gv.x + bev.x;
            float g1 = (h1 - mu) * inv * gv.y + bev.y;
            float g2 = (h2 - mu) * inv * gv.z + bev.z;
            float g3 = (h3 - mu) * inv * gv.w + bev.w;
            *(float4*)&hs[(trr + r) * AS_STRIDE + tc * 4] =
                make_float4(silu_f(g0), silu_f(g1), silu_f(g2), silu_f(g3));
        }
        __syncthreads();

        // ---- GEMM2: o[r][c] = silu(hs[r] . W2[:,c] + b2) ----
        unsigned long long acc2[4][2];
        #pragma unroll
        for (int r = 0; r < 4; ++r) { acc2[r][0] = 0ull; acc2[r][1] = 0ull; }

        const float* a0 = &hs[(trr + 0) * AS_STRIDE];
        const float* a1 = &hs[(trr + 1) * AS_STRIDE];
        const float* a2 = &hs[(trr + 2) * AS_STRIDE];
        const float* a3 = &hs[(trr + 3) * AS_STRIDE];
        const float* w2p = &W2s[tc * 4];

        #pragma unroll 8
        for (int k = 0; k < OUT_DIM; ++k) {
            ulonglong2 w = *(const ulonglong2*)(w2p + k * OUT_DIM);
            unsigned long long xx0 = pack_dup(a0[k]);
            unsigned long long xx1 = pack_dup(a1[k]);
            unsigned long long xx2 = pack_dup(a2[k]);
            unsigned long long xx3 = pack_dup(a3[k]);
            ffma2(acc2[0][0], w.x, xx0); ffma2(acc2[0][1], w.y, xx0);
            ffma2(acc2[1][0], w.x, xx1); ffma2(acc2[1][1], w.y, xx1);
            ffma2(acc2[2][0], w.x, xx2); ffma2(acc2[2][1], w.y, xx2);
            ffma2(acc2[3][0], w.x, xx3); ffma2(acc2[3][1], w.y, xx3);
        }

        #pragma unroll
        for (int r = 0; r < 4; ++r) {
            float2 a01 = unpack2(acc2[r][0]);
            float2 a23 = unpack2(acc2[r][1]);
            float o0 = silu_f(a01.x + b2v.x);
            float o1 = silu_f(a01.y + b2v.y);
            float o2 = silu_f(a23.x + b2v.z);
            float o3 = silu_f(a23.y + b2v.w);
            *(float4*)(out + (long)(rowbase + trr + r) * OUT_DIM + tc * 4) =
                make_float4(o0, o1, o2, o3);
        }
        // no trailing sync needed: next-iter hs writes are fenced by the
        // post-xs-load __syncthreads, and xs writes by the post-hs __syncthreads.
    }
}

extern "C" void kernel_launch(void* const* d_in, const int* in_sizes, int n_in,
                              void* d_out, int out_size)
{
    const float* src = (const float*)d_in[0];
    const float* edg = (const float*)d_in[1];
    const float* W1  = (const float*)d_in[2];
    const float* b1  = (const float*)d_in[3];
    const float* g   = (const float*)d_in[4];
    const float* be  = (const float*)d_in[5];
    const float* W2  = (const float*)d_in[6];
    const float* b2  = (const float*)d_in[7];
    float* out = (float*)d_out;

    const int nrows = in_sizes[0] / NODE_DIM;   // 500000

    const int smem_bytes = (IN_DIM * OUT_DIM + OUT_DIM * OUT_DIM +
                            TILE_R * XS_STRIDE + TILE_R * AS_STRIDE +
                            4 * OUT_DIM) * (int)sizeof(float);   // 208384 B

    cudaFuncSetAttribute(edge_mlp_kernel,
                         cudaFuncAttributeMaxDynamicSharedMemorySize, smem_bytes);

    int dev = 0, sms = 148;
    cudaGetDevice(&dev);
    cudaDeviceGetAttribute(&sms, cudaDevAttrMultiProcessorCount, dev);

    edge_mlp_kernel<<<sms, THREADS, smem_bytes>>>(src, edg, W1, b1, g, be, W2, b2, out, nrows);
}

// round 8
// speedup vs baseline: 2.3449x; 2.3449x over previous
#include <cuda_runtime.h>
#include <cuda_bf16.h>
#include <cstdint>

#define THREADS  256
#define TILE_M   64
#define NODE_DIM 128
#define EDGE_DIM 64
#define K1       192
#define K2       128
#define NN       128

// bf16-element strides (padded so row stride % 128B == 16B -> conflict-free ldmatrix)
#define XS_STR   200   // 400 bytes per row (k up to 192)
#define W1_STR   200   // 400 bytes per row (k = 192)
#define W2_STR   136   // 272 bytes per row (k = 128)

// ---- SMEM byte offsets ----
#define W1H_OFF   0                         // 128*400 = 51200
#define W1L_OFF   51200
#define W2H_OFF   102400                    // 128*272 = 34816
#define W2L_OFF   137216
#define XSH_OFF   172032                    // 64*400 = 25600
#define XSL_OFF   197632
#define COLT_OFF  223232                    // float4[128] = 2048
#define PSUM_OFF  225280                    // float[128] = 512
#define SMEM_BYTES 225792

// ============ PTX helpers (baseline mma.sync path — legal on compute_103) ============
__device__ __forceinline__ uint32_t smem_u32(const void* p) {
    uint32_t a;
    asm("{ .reg .u64 t; cvta.to.shared.u64 t, %1; cvt.u32.u64 %0, t; }" : "=r"(a) : "l"(p));
    return a;
}
__device__ __forceinline__ void ldsm_x4(uint32_t* r, uint32_t addr) {
    asm volatile("ldmatrix.sync.aligned.m8n8.x4.shared.b16 {%0,%1,%2,%3}, [%4];"
        : "=r"(r[0]), "=r"(r[1]), "=r"(r[2]), "=r"(r[3]) : "r"(addr));
}
__device__ __forceinline__ void mma_bf16(float* d, const uint32_t* a, const uint32_t* b) {
    asm volatile("mma.sync.aligned.m16n8k16.row.col.f32.bf16.bf16.f32 "
        "{%0,%1,%2,%3}, {%4,%5,%6,%7}, {%8,%9}, {%0,%1,%2,%3};"
        : "+f"(d[0]), "+f"(d[1]), "+f"(d[2]), "+f"(d[3])
        : "r"(a[0]), "r"(a[1]), "r"(a[2]), "r"(a[3]), "r"(b[0]), "r"(b[1]));
}
// packed bf16x2: low half = e0 (even/first element), high half = e1
__device__ __forceinline__ uint32_t pack_bf16x2(float e0, float e1) {
    uint32_t r;
    asm("cvt.rn.bf16x2.f32 %0, %1, %2;" : "=r"(r) : "f"(e1), "f"(e0));
    return r;
}
__device__ __forceinline__ uint16_t bf16_bits(float x) {
    uint16_t u;
    asm("cvt.rn.bf16.f32 %0, %1;" : "=h"(u) : "f"(x));
    return u;
}
__device__ __forceinline__ float silu_f(float g) {
    return __fdividef(g, 1.0f + __expf(-g));
}

__global__ __launch_bounds__(THREADS, 1)
void edge_mlp_hmma_kernel(const float* __restrict__ src,
                          const float* __restrict__ edg,
                          const float* __restrict__ W1,
                          const float* __restrict__ b1,
                          const float* __restrict__ gamma,
                          const float* __restrict__ beta,
                          const float* __restrict__ W2,
                          const float* __restrict__ b2,
                          float* __restrict__ out,
                          int nrows, int ntiles)
{
    extern __shared__ char smem[];
    const uint32_t sb = smem_u32(smem);
    const int tid  = threadIdx.x;
    const int lane = tid & 31;
    const int wid  = tid >> 5;
    const int rg = wid >> 2;            // rowgroup 0/1 -> rows [rg*32, rg*32+32)
    const int cg = wid & 3;             // colgroup 0..3 -> cols [cg*32, cg*32+32)
    const int rb = rg * 32;
    const int nb = cg * 32;

    // ---- one-time: weights fp32 [k][n] -> bf16 hi/lo transposed [n][k] ----
    for (int i = tid; i < K1 * NN; i += THREADS) {
        int k = i >> 7, n = i & 127;
        float v = W1[i];
        uint16_t hb = bf16_bits(v);
        uint16_t lb = bf16_bits(v - __uint_as_float((uint32_t)hb << 16));
        *(uint16_t*)(smem + W1H_OFF + n * 400 + k * 2) = hb;
        *(uint16_t*)(smem + W1L_OFF + n * 400 + k * 2) = lb;
    }
    for (int i = tid; i < K2 * NN; i += THREADS) {
        int k = i >> 7, n = i & 127;
        float v = W2[i];
        uint16_t hb = bf16_bits(v);
        uint16_t lb = bf16_bits(v - __uint_as_float((uint32_t)hb << 16));
        *(uint16_t*)(smem + W2H_OFF + n * 272 + k * 2) = hb;
        *(uint16_t*)(smem + W2L_OFF + n * 272 + k * 2) = lb;
    }
    if (tid < NN)
        ((float4*)(smem + COLT_OFF))[tid] =
            make_float4(b1[tid], gamma[tid], beta[tid], b2[tid]);
    if (tid < 128) ((float*)(smem + PSUM_OFF))[tid] = 0.f;
    __syncthreads();

    // ---- per-thread fragment byte offsets ----
    // A (and h) fragments from xs arrays, stride 400B
    const uint32_t aoff = (uint32_t)(rb + (lane & 15)) * 400 + (uint32_t)((lane >> 4) * 8) * 2;
    // B fragments from transposed weight arrays
    const int b_n = nb + (lane & 7) + ((lane >> 4) & 1) * 8;
    const int b_k = ((lane >> 3) & 1) * 8;
    const uint32_t boff1 = (uint32_t)b_n * 400 + (uint32_t)b_k * 2;
    const uint32_t boff2 = (uint32_t)b_n * 272 + (uint32_t)b_k * 2;

    const int q = lane >> 2;
    const int cpair = (lane & 3) * 2;
    const float4* colt = (const float4*)(smem + COLT_OFF);
    float* ps = (float*)(smem + PSUM_OFF);

    for (int tile = blockIdx.x; tile < ntiles; tile += gridDim.x) {
        const int tbase = tile * TILE_M;

        // ---- stage x tile: 64 rows x 192 cols, fp32 -> bf16 hi/lo ----
        #pragma unroll
        for (int it = 0; it < 12; ++it) {
            int c   = it * THREADS + tid;        // 0..3071 float4 slots
            int row = c / 48;
            int kg  = c - row * 48;              // 0..47
            int rl  = tbase + row; if (rl >= nrows) rl = nrows - 1;
            float4 v = (kg < 32)
                ? ((const float4*)(src + (size_t)rl * NODE_DIM))[kg]
                : ((const float4*)(edg + (size_t)rl * EDGE_DIM))[kg - 32];
            uint32_t h01 = pack_bf16x2(v.x, v.y);
            uint32_t h23 = pack_bf16x2(v.z, v.w);
            float r0 = v.x - __uint_as_float(h01 << 16);
            float r1 = v.y - __uint_as_float(h01 & 0xffff0000u);
            float r2 = v.z - __uint_as_float(h23 << 16);
            float r3 = v.w - __uint_as_float(h23 & 0xffff0000u);
            uint32_t l01 = pack_bf16x2(r0, r1);
            uint32_t l23 = pack_bf16x2(r2, r3);
            *(uint64_t*)(smem + XSH_OFF + row * 400 + kg * 8) = ((uint64_t)h23 << 32) | h01;
            *(uint64_t*)(smem + XSL_OFF + row * 400 + kg * 8) = ((uint64_t)l23 << 32) | l01;
        }
        __syncthreads();

        // ---- GEMM1: K=192, bf16x3 split (hi*hi + lo*hi + hi*lo) ----
        float acc[2][4][4];
        #pragma unroll
        for (int m = 0; m < 2; ++m)
            #pragma unroll
            for (int f = 0; f < 4; ++f)
                #pragma unroll
                for (int u = 0; u < 4; ++u) acc[m][f][u] = 0.f;

        #pragma unroll
        for (int s = 0; s < 12; ++s) {
            const uint32_t so = s * 32;
            uint32_t ah[2][4], al[2][4], bh[8], bl[8];
            ldsm_x4(ah[0], sb + XSH_OFF + aoff + so);
            ldsm_x4(al[0], sb + XSL_OFF + aoff + so);
            ldsm_x4(ah[1], sb + XSH_OFF + aoff + 6400 + so);
            ldsm_x4(al[1], sb + XSL_OFF + aoff + 6400 + so);
            ldsm_x4(bh,     sb + W1H_OFF + boff1 + so);
            ldsm_x4(bh + 4, sb + W1H_OFF + boff1 + 6400 + so);
            ldsm_x4(bl,     sb + W1L_OFF + boff1 + so);
            ldsm_x4(bl + 4, sb + W1L_OFF + boff1 + 6400 + so);
            #pragma unroll
            for (int m = 0; m < 2; ++m)
                #pragma unroll
                for (int f = 0; f < 4; ++f) {
                    mma_bf16(acc[m][f], ah[m], &bh[2 * f]);
                    mma_bf16(acc[m][f], al[m], &bh[2 * f]);
                    mma_bf16(acc[m][f], ah[m], &bl[2 * f]);
                }
        }

        // ---- epilogue1: +b1, LN stats (quad shfl + smem atomics), sync ----
        #pragma unroll
        for (int m = 0; m < 2; ++m)
            #pragma unroll
            for (int h = 0; h < 2; ++h) {
                float s = 0.f, ss = 0.f;
                #pragma unroll
                for (int f = 0; f < 4; ++f) {
                    int col = nb + f * 8 + cpair;
                    float h0 = acc[m][f][2 * h]     + colt[col].x;
                    float h1 = acc[m][f][2 * h + 1] + colt[col + 1].x;
                    acc[m][f][2 * h] = h0; acc[m][f][2 * h + 1] = h1;
                    s += h0 + h1;  ss += h0 * h0 + h1 * h1;
                }
                s  += __shfl_xor_sync(0xffffffffu, s, 1);
                s  += __shfl_xor_sync(0xffffffffu, s, 2);
                ss += __shfl_xor_sync(0xffffffffu, ss, 1);
                ss += __shfl_xor_sync(0xffffffffu, ss, 2);
                if ((lane & 3) == 0) {
                    int row = rb + m * 16 + h * 8 + q;
                    atomicAdd(&ps[2 * row], s);
                    atomicAdd(&ps[2 * row + 1], ss);
                }
            }
        __syncthreads();

        // ---- LN + SiLU + split -> restage into xs arrays (as h tile) ----
        #pragma unroll
        for (int m = 0; m < 2; ++m)
            #pragma unroll
            for (int h = 0; h < 2; ++h) {
                int row = rb + m * 16 + h * 8 + q;
                float mu  = ps[2 * row] * (1.0f / 128.0f);
                float inv = rsqrtf(ps[2 * row + 1] * (1.0f / 128.0f) - mu * mu + 1e-5f);
                #pragma unroll
                for (int f = 0; f < 4; ++f) {
                    int col = nb + f * 8 + cpair;
                    float4 cA = colt[col], cB = colt[col + 1];
                    float g0 = (acc[m][f][2 * h]     - mu) * inv * cA.y + cA.z;
                    float g1 = (acc[m][f][2 * h + 1] - mu) * inv * cB.y + cB.z;
                    float a0 = silu_f(g0), a1 = silu_f(g1);
                    uint32_t hw = pack_bf16x2(a0, a1);
                    float r0 = a0 - __uint_as_float(hw << 16);
                    float r1 = a1 - __uint_as_float(hw & 0xffff0000u);
                    uint32_t lw = pack_bf16x2(r0, r1);
                    *(uint32_t*)(smem + XSH_OFF + row * 400 + col * 2) = hw;
                    *(uint32_t*)(smem + XSL_OFF + row * 400 + col * 2) = lw;
                }
            }
        __syncthreads();
        if (tid < 128) ps[tid] = 0.f;   // reset stats for next tile (sealed by loop-end sync)

        // ---- GEMM2: K=128 ----
        float ac2[2][4][4];
        #pragma unroll
        for (int m = 0; m < 2; ++m)
            #pragma unroll
            for (int f = 0; f < 4; ++f)
                #pragma unroll
                for (int u = 0; u < 4; ++u) ac2[m][f][u] = 0.f;

        #pragma unroll
        for (int s = 0; s < 8; ++s) {
            const uint32_t so = s * 32;
            uint32_t ah[2][4], al[2][4], bh[8], bl[8];
            ldsm_x4(ah[0], sb + XSH_OFF + aoff + so);
            ldsm_x4(al[0], sb + XSL_OFF + aoff + so);
            ldsm_x4(ah[1], sb + XSH_OFF + aoff + 6400 + so);
            ldsm_x4(al[1], sb + XSL_OFF + aoff + 6400 + so);
            ldsm_x4(bh,     sb + W2H_OFF + boff2 + so);
            ldsm_x4(bh + 4, sb + W2H_OFF + boff2 + 4352 + so);
            ldsm_x4(bl,     sb + W2L_OFF + boff2 + so);
            ldsm_x4(bl + 4, sb + W2L_OFF + boff2 + 4352 + so);
            #pragma unroll
            for (int m = 0; m < 2; ++m)
                #pragma unroll
                for (int f = 0; f < 4; ++f) {
                    mma_bf16(ac2[m][f], ah[m], &bh[2 * f]);
                    mma_bf16(ac2[m][f], al[m], &bh[2 * f]);
                    mma_bf16(ac2[m][f], ah[m], &bl[2 * f]);
                }
        }

        // ---- epilogue2: +b2, SiLU, store ----
        #pragma unroll
        for (int m = 0; m < 2; ++m)
            #pragma unroll
            for (int h = 0; h < 2; ++h) {
                int row = rb + m * 16 + h * 8 + q;
                int grow = tbase + row;
                if (grow < nrows) {
                    #pragma unroll
                    for (int f = 0; f < 4; ++f) {
                        int col = nb + f * 8 + cpair;
                        float o0 = silu_f(ac2[m][f][2 * h]     + colt[col].w);
                        float o1 = silu_f(ac2[m][f][2 * h + 1] + colt[col + 1].w);
                        *(float2*)(out + (size_t)grow * NN + col) = make_float2(o0, o1);
                    }
                }
            }
        __syncthreads();   // protect xs restaging + psum reset vs next tile
    }
}

extern "C" void kernel_launch(void* const* d_in, const int* in_sizes, int n_in,
                              void* d_out, int out_size)
{
    const float* src = (const float*)d_in[0];
    const float* edg = (const float*)d_in[1];
    const float* W1  = (const float*)d_in[2];
    const float* b1  = (const float*)d_in[3];
    const float* gm  = (const float*)d_in[4];
    const float* be  = (const float*)d_in[5];
    const float* W2  = (const float*)d_in[6];
    const float* b2  = (const float*)d_in[7];
    float* out = (float*)d_out;

    const int nrows  = in_sizes[0] / NODE_DIM;
    const int ntiles = (nrows + TILE_M - 1) / TILE_M;

    cudaFuncSetAttribute(edge_mlp_hmma_kernel,
                         cudaFuncAttributeMaxDynamicSharedMemorySize, SMEM_BYTES);

    int dev = 0, sms = 148;
    cudaGetDevice(&dev);
    cudaDeviceGetAttribute(&sms, cudaDevAttrMultiProcessorCount, dev);
    int grid = (sms < ntiles) ? sms : ntiles;

    edge_mlp_hmma_kernel<<<grid, THREADS, SMEM_BYTES>>>(
        src, edg, W1, b1, gm, be, W2, b2, out, nrows, ntiles);
}

// round 9
// speedup vs baseline: 2.5856x; 1.1026x over previous
#include <cuda_runtime.h>
#include <cuda_bf16.h>
#include <cstdint>

#define THREADS  512
#define TILE_M   64
#define NODE_DIM 128
#define EDGE_DIM 64
#define K1       192
#define K2       128
#define NN       128

// ---- SMEM byte offsets (row strides 400B / 272B: stride%128==16 -> conflict-free ldmatrix) ----
#define W1H_OFF   0                         // 128*400 = 51200
#define W1L_OFF   51200
#define W2H_OFF   102400                    // 128*272 = 34816
#define W2L_OFF   137216
#define XSH_OFF   172032                    // 64*400 = 25600
#define XSL_OFF   197632
#define COLT_OFF  223232                    // float4[128] = 2048
#define PSUM_OFF  225280                    // float[128] = 512
#define SMEM_BYTES 225792

// ============ PTX helpers (mma.sync path — legal on compute_103) ============
__device__ __forceinline__ uint32_t smem_u32(const void* p) {
    uint32_t a;
    asm("{ .reg .u64 t; cvta.to.shared.u64 t, %1; cvt.u32.u64 %0, t; }" : "=r"(a) : "l"(p));
    return a;
}
__device__ __forceinline__ void ldsm_x4(uint32_t* r, uint32_t addr) {
    asm volatile("ldmatrix.sync.aligned.m8n8.x4.shared.b16 {%0,%1,%2,%3}, [%4];"
        : "=r"(r[0]), "=r"(r[1]), "=r"(r[2]), "=r"(r[3]) : "r"(addr));
}
__device__ __forceinline__ void mma_bf16(float* d, const uint32_t* a, const uint32_t* b) {
    asm volatile("mma.sync.aligned.m16n8k16.row.col.f32.bf16.bf16.f32 "
        "{%0,%1,%2,%3}, {%4,%5,%6,%7}, {%8,%9}, {%0,%1,%2,%3};"
        : "+f"(d[0]), "+f"(d[1]), "+f"(d[2]), "+f"(d[3])
        : "r"(a[0]), "r"(a[1]), "r"(a[2]), "r"(a[3]), "r"(b[0]), "r"(b[1]));
}
__device__ __forceinline__ uint32_t pack_bf16x2(float e0, float e1) {
    uint32_t r;
    asm("cvt.rn.bf16x2.f32 %0, %1, %2;" : "=r"(r) : "f"(e1), "f"(e0));
    return r;
}
__device__ __forceinline__ uint16_t bf16_bits(float x) {
    uint16_t u;
    asm("cvt.rn.bf16.f32 %0, %1;" : "=h"(u) : "f"(x));
    return u;
}
__device__ __forceinline__ float silu_f(float g) {
    return __fdividef(g, 1.0f + __expf(-g));
}

__global__ __launch_bounds__(THREADS, 1)
void edge_mlp_hmma_kernel(const float* __restrict__ src,
                          const float* __restrict__ edg,
                          const float* __restrict__ W1,
                          const float* __restrict__ b1,
                          const float* __restrict__ gamma,
                          const float* __restrict__ beta,
                          const float* __restrict__ W2,
                          const float* __restrict__ b2,
                          float* __restrict__ out,
                          int nrows, int ntiles)
{
    extern __shared__ char smem[];
    const uint32_t sb = smem_u32(smem);
    const int tid  = threadIdx.x;
    const int lane = tid & 31;
    const int wid  = tid >> 5;
    const int rg = wid >> 2;            // rowgroup 0..3 -> rows [rg*16, rg*16+16)
    const int cg = wid & 3;             // colgroup 0..3 -> cols [cg*32, cg*32+32)
    const int rb = rg * 16;
    const int nb = cg * 32;

    // ---- one-time: weights fp32 [k][n] -> bf16 hi/lo transposed [n][k] ----
    for (int i = tid; i < K1 * NN; i += THREADS) {
        int k = i >> 7, n = i & 127;
        float v = W1[i];
        uint16_t hb = bf16_bits(v);
        uint16_t lb = bf16_bits(v - __uint_as_float((uint32_t)hb << 16));
        *(uint16_t*)(smem + W1H_OFF + n * 400 + k * 2) = hb;
        *(uint16_t*)(smem + W1L_OFF + n * 400 + k * 2) = lb;
    }
    for (int i = tid; i < K2 * NN; i += THREADS) {
        int k = i >> 7, n = i & 127;
        float v = W2[i];
        uint16_t hb = bf16_bits(v);
        uint16_t lb = bf16_bits(v - __uint_as_float((uint32_t)hb << 16));
        *(uint16_t*)(smem + W2H_OFF + n * 272 + k * 2) = hb;
        *(uint16_t*)(smem + W2L_OFF + n * 272 + k * 2) = lb;
    }
    if (tid < NN)
        ((float4*)(smem + COLT_OFF))[tid] =
            make_float4(b1[tid], gamma[tid], beta[tid], b2[tid]);
    if (tid < 128) ((float*)(smem + PSUM_OFF))[tid] = 0.f;
    __syncthreads();

    // ---- per-thread fragment byte offsets ----
    const uint32_t aoff = (uint32_t)(rb + (lane & 15)) * 400 + (uint32_t)((lane >> 4) * 8) * 2;
    const int b_n = nb + (lane & 7) + ((lane >> 4) & 1) * 8;
    const int b_k = ((lane >> 3) & 1) * 8;
    const uint32_t boff1 = (uint32_t)b_n * 400 + (uint32_t)b_k * 2;
    const uint32_t boff2 = (uint32_t)b_n * 272 + (uint32_t)b_k * 2;

    const int q = lane >> 2;
    const int cpair = (lane & 3) * 2;
    const float4* colt = (const float4*)(smem + COLT_OFF);
    float* ps = (float*)(smem + PSUM_OFF);

    for (int tile = blockIdx.x; tile < ntiles; tile += gridDim.x) {
        const int tbase = tile * TILE_M;

        // ---- stage x tile: 64 rows x 192 cols, fp32 -> bf16 hi/lo ----
        #pragma unroll
        for (int it = 0; it < 6; ++it) {
            int c   = it * THREADS + tid;        // 0..3071 float4 slots
            int row = c / 48;
            int kg  = c - row * 48;              // 0..47
            int rl  = tbase + row; if (rl >= nrows) rl = nrows - 1;
            float4 v = (kg < 32)
                ? ((const float4*)(src + (size_t)rl * NODE_DIM))[kg]
                : ((const float4*)(edg + (size_t)rl * EDGE_DIM))[kg - 32];
            uint32_t h01 = pack_bf16x2(v.x, v.y);
            uint32_t h23 = pack_bf16x2(v.z, v.w);
            float r0 = v.x - __uint_as_float(h01 << 16);
            float r1 = v.y - __uint_as_float(h01 & 0xffff0000u);
            float r2 = v.z - __uint_as_float(h23 << 16);
            float r3 = v.w - __uint_as_float(h23 & 0xffff0000u);
            uint32_t l01 = pack_bf16x2(r0, r1);
            uint32_t l23 = pack_bf16x2(r2, r3);
            *(uint64_t*)(smem + XSH_OFF + row * 400 + kg * 8) = ((uint64_t)h23 << 32) | h01;
            *(uint64_t*)(smem + XSL_OFF + row * 400 + kg * 8) = ((uint64_t)l23 << 32) | l01;
        }
        __syncthreads();

        // ---- GEMM1: K=192, bf16x3 split (hi*hi + lo*hi + hi*lo) ----
        float acc[4][4];
        #pragma unroll
        for (int f = 0; f < 4; ++f)
            #pragma unroll
            for (int u = 0; u < 4; ++u) acc[f][u] = 0.f;

        #pragma unroll
        for (int s = 0; s < 12; ++s) {
            const uint32_t so = s * 32;
            uint32_t ah[4], al[4], bh[8], bl[8];
            ldsm_x4(ah, sb + XSH_OFF + aoff + so);
            ldsm_x4(al, sb + XSL_OFF + aoff + so);
            ldsm_x4(bh,     sb + W1H_OFF + boff1 + so);
            ldsm_x4(bh + 4, sb + W1H_OFF + boff1 + 6400 + so);
            ldsm_x4(bl,     sb + W1L_OFF + boff1 + so);
            ldsm_x4(bl + 4, sb + W1L_OFF + boff1 + 6400 + so);
            #pragma unroll
            for (int f = 0; f < 4; ++f) {
                mma_bf16(acc[f], ah, &bh[2 * f]);
                mma_bf16(acc[f], al, &bh[2 * f]);
                mma_bf16(acc[f], ah, &bl[2 * f]);
            }
        }

        // ---- epilogue1: +b1, LN stats (quad shfl + smem atomics), sync ----
        #pragma unroll
        for (int h = 0; h < 2; ++h) {
            float s = 0.f, ss = 0.f;
            #pragma unroll
            for (int f = 0; f < 4; ++f) {
                int col = nb + f * 8 + cpair;
                float h0 = acc[f][2 * h]     + colt[col].x;
                float h1 = acc[f][2 * h + 1] + colt[col + 1].x;
                acc[f][2 * h] = h0; acc[f][2 * h + 1] = h1;
                s += h0 + h1;  ss += h0 * h0 + h1 * h1;
            }
            s  += __shfl_xor_sync(0xffffffffu, s, 1);
            s  += __shfl_xor_sync(0xffffffffu, s, 2);
            ss += __shfl_xor_sync(0xffffffffu, ss, 1);
            ss += __shfl_xor_sync(0xffffffffu, ss, 2);
            if ((lane & 3) == 0) {
                int row = rb + h * 8 + q;
                atomicAdd(&ps[2 * row], s);
                atomicAdd(&ps[2 * row + 1], ss);
            }
        }
        __syncthreads();

        // ---- LN + SiLU + split -> restage into xs arrays (as h tile) ----
        #pragma unroll
        for (int h = 0; h < 2; ++h) {
            int row = rb + h * 8 + q;
            float mu  = ps[2 * row] * (1.0f / 128.0f);
            float inv = rsqrtf(ps[2 * row + 1] * (1.0f / 128.0f) - mu * mu + 1e-5f);
            #pragma unroll
            for (int f = 0; f < 4; ++f) {
                int col = nb + f * 8 + cpair;
                float4 cA = colt[col], cB = colt[col + 1];
                float g0 = (acc[f][2 * h]     - mu) * inv * cA.y + cA.z;
                float g1 = (acc[f][2 * h + 1] - mu) * inv * cB.y + cB.z;
                float a0 = silu_f(g0), a1 = silu_f(g1);
                uint32_t hw = pack_bf16x2(a0, a1);
                float r0 = a0 - __uint_as_float(hw << 16);
                float r1 = a1 - __uint_as_float(hw & 0xffff0000u);
                uint32_t lw = pack_bf16x2(r0, r1);
                *(uint32_t*)(smem + XSH_OFF + row * 400 + col * 2) = hw;
                *(uint32_t*)(smem + XSL_OFF + row * 400 + col * 2) = lw;
            }
        }
        __syncthreads();
        if (tid < 128) ps[tid] = 0.f;   // reset stats for next tile (sealed by loop-end sync)

        // ---- GEMM2: K=128 ----
        float ac2[4][4];
        #pragma unroll
        for (int f = 0; f < 4; ++f)
            #pragma unroll
            for (int u = 0; u < 4; ++u) ac2[f][u] = 0.f;

        #pragma unroll
        for (int s = 0; s < 8; ++s) {
            const uint32_t so = s * 32;
            uint32_t ah[4], al[4], bh[8], bl[8];
            ldsm_x4(ah, sb + XSH_OFF + aoff + so);
            ldsm_x4(al, sb + XSL_OFF + aoff + so);
            ldsm_x4(bh,     sb + W2H_OFF + boff2 + so);
            ldsm_x4(bh + 4, sb + W2H_OFF + boff2 + 4352 + so);
            ldsm_x4(bl,     sb + W2L_OFF + boff2 + so);
            ldsm_x4(bl + 4, sb + W2L_OFF + boff2 + 4352 + so);
            #pragma unroll
            for (int f = 0; f < 4; ++f) {
                mma_bf16(ac2[f], ah, &bh[2 * f]);
                mma_bf16(ac2[f], al, &bh[2 * f]);
                mma_bf16(ac2[f], ah, &bl[2 * f]);
            }
        }

        // ---- epilogue2: +b2, SiLU, store ----
        #pragma unroll
        for (int h = 0; h < 2; ++h) {
            int row = rb + h * 8 + q;
            int grow = tbase + row;
            if (grow < nrows) {
                #pragma unroll
                for (int f = 0; f < 4; ++f) {
                    int col = nb + f * 8 + cpair;
                    float o0 = silu_f(ac2[f][2 * h]     + colt[col].w);
                    float o1 = silu_f(ac2[f][2 * h + 1] + colt[col + 1].w);
                    *(float2*)(out + (size_t)grow * NN + col) = make_float2(o0, o1);
                }
            }
        }
        __syncthreads();   // protect xs restaging + psum reset vs next tile
    }
}

extern "C" void kernel_launch(void* const* d_in, const int* in_sizes, int n_in,
                              void* d_out, int out_size)
{
    const float* src = (const float*)d_in[0];
    const float* edg = (const float*)d_in[1];
    const float* W1  = (const float*)d_in[2];
    const float* b1  = (const float*)d_in[3];
    const float* gm  = (const float*)d_in[4];
    const float* be  = (const float*)d_in[5];
    const float* W2  = (const float*)d_in[6];
    const float* b2  = (const float*)d_in[7];
    float* out = (float*)d_out;

    const int nrows  = in_sizes[0] / NODE_DIM;
    const int ntiles = (nrows + TILE_M - 1) / TILE_M;

    cudaFuncSetAttribute(edge_mlp_hmma_kernel,
                         cudaFuncAttributeMaxDynamicSharedMemorySize, SMEM_BYTES);

    int dev = 0, sms = 148;
    cudaGetDevice(&dev);
    cudaDeviceGetAttribute(&sms, cudaDevAttrMultiProcessorCount, dev);
    int grid = (sms < ntiles) ? sms : ntiles;

    edge_mlp_hmma_kernel<<<grid, THREADS, SMEM_BYTES>>>(
        src, edg, W1, b1, gm, be, W2, b2, out, nrows, ntiles);
}

// round 11
// speedup vs baseline: 2.9651x; 1.1468x over previous
#include <cuda_runtime.h>
#include <cuda_bf16.h>
#include <cstdint>

#define THREADS  512
#define TILE_M   64
#define NODE_DIM 128
#define EDGE_DIM 64
#define K1       192
#define K2       128
#define NN       128

// ---- SMEM byte offsets (row strides 400B / 272B: stride%128==16 -> conflict-free ldmatrix) ----
#define W1H_OFF   0                         // 128*400 = 51200
#define W1L_OFF   51200
#define W2H_OFF   102400                    // 128*272 = 34816
#define W2L_OFF   137216
#define XSH_OFF   172032                    // 64*400 = 25600
#define XSL_OFF   197632
#define COLT_OFF  223232                    // float4[128] = 2048
#define PSUM_OFF  225280                    // float2[64][4] = 2048
#define SMEM_BYTES 227328

// ============ PTX helpers (mma.sync path — legal on compute_103) ============
__device__ __forceinline__ uint32_t smem_u32(const void* p) {
    uint32_t a;
    asm("{ .reg .u64 t; cvta.to.shared.u64 t, %1; cvt.u32.u64 %0, t; }" : "=r"(a) : "l"(p));
    return a;
}
__device__ __forceinline__ void ldsm_x4(uint32_t* r, uint32_t addr) {
    asm volatile("ldmatrix.sync.aligned.m8n8.x4.shared.b16 {%0,%1,%2,%3}, [%4];"
        : "=r"(r[0]), "=r"(r[1]), "=r"(r[2]), "=r"(r[3]) : "r"(addr));
}
__device__ __forceinline__ void mma_bf16(float* d, const uint32_t* a, const uint32_t* b) {
    asm volatile("mma.sync.aligned.m16n8k16.row.col.f32.bf16.bf16.f32 "
        "{%0,%1,%2,%3}, {%4,%5,%6,%7}, {%8,%9}, {%0,%1,%2,%3};"
        : "+f"(d[0]), "+f"(d[1]), "+f"(d[2]), "+f"(d[3])
        : "r"(a[0]), "r"(a[1]), "r"(a[2]), "r"(a[3]), "r"(b[0]), "r"(b[1]));
}
__device__ __forceinline__ uint32_t pack_bf16x2(float e0, float e1) {
    uint32_t r;
    asm("cvt.rn.bf16x2.f32 %0, %1, %2;" : "=r"(r) : "f"(e1), "f"(e0));
    return r;
}
__device__ __forceinline__ uint16_t bf16_bits(float x) {
    uint16_t u;
    asm("cvt.rn.bf16.f32 %0, %1;" : "=h"(u) : "f"(x));
    return u;
}
// silu(x) = x * sigmoid(x) = 0.5*x*(1 + tanh(x/2)) — 1 MUFU instead of 2
__device__ __forceinline__ float silu_f(float x) {
    float t;
    asm("tanh.approx.f32 %0, %1;" : "=f"(t) : "f"(x * 0.5f));
    return 0.5f * x * (1.0f + t);
}

// prefetch one x-tile (64 x 192 fp32) into 6 float4 regs per thread
__device__ __forceinline__ void ld_tile6(const float* __restrict__ src,
                                         const float* __restrict__ edg,
                                         int tbase, int nrows, int tid, float4* pv) {
    #pragma unroll
    for (int it = 0; it < 6; ++it) {
        int c   = it * THREADS + tid;
        int row = c / 48;
        int kg  = c - row * 48;
        int rl  = tbase + row; if (rl >= nrows) rl = nrows - 1;
        pv[it] = (kg < 32)
            ? ((const float4*)(src + (size_t)rl * NODE_DIM))[kg]
            : ((const float4*)(edg + (size_t)rl * EDGE_DIM))[kg - 32];
    }
}

__global__ __launch_bounds__(THREADS, 1)
void edge_mlp_hmma_kernel(const float* __restrict__ src,
                          const float* __restrict__ edg,
                          const float* __restrict__ W1,
                          const float* __restrict__ b1,
                          const float* __restrict__ gamma,
                          const float* __restrict__ beta,
                          const float* __restrict__ W2,
                          const float* __restrict__ b2,
                          float* __restrict__ out,
                          int nrows, int ntiles)
{
    extern __shared__ char smem[];
    const uint32_t sb = smem_u32(smem);
    const int tid  = threadIdx.x;
    const int lane = tid & 31;
    const int wid  = tid >> 5;
    const int rg = wid >> 2;            // rowgroup 0..3 -> rows [rg*16, rg*16+16)
    const int cg = wid & 3;             // colgroup 0..3 -> cols [cg*32, cg*32+32)
    const int rb = rg * 16;
    const int nb = cg * 32;

    // ---- one-time: weights fp32 [k][n] -> bf16 hi/lo transposed [n][k] ----
    for (int i = tid; i < K1 * NN; i += THREADS) {
        int k = i >> 7, n = i & 127;
        float v = W1[i];
        uint16_t hb = bf16_bits(v);
        uint16_t lb = bf16_bits(v - __uint_as_float((uint32_t)hb << 16));
        *(uint16_t*)(smem + W1H_OFF + n * 400 + k * 2) = hb;
        *(uint16_t*)(smem + W1L_OFF + n * 400 + k * 2) = lb;
    }
    for (int i = tid; i < K2 * NN; i += THREADS) {
        int k = i >> 7, n = i & 127;
        float v = W2[i];
        uint16_t hb = bf16_bits(v);
        uint16_t lb = bf16_bits(v - __uint_as_float((uint32_t)hb << 16));
        *(uint16_t*)(smem + W2H_OFF + n * 272 + k * 2) = hb;
        *(uint16_t*)(smem + W2L_OFF + n * 272 + k * 2) = lb;
    }
    if (tid < NN)
        ((float4*)(smem + COLT_OFF))[tid] =
            make_float4(b1[tid], gamma[tid], beta[tid], b2[tid]);
    __syncthreads();

    // ---- per-thread fragment byte offsets ----
    const uint32_t aoff = (uint32_t)(rb + (lane & 15)) * 400 + (uint32_t)((lane >> 4) * 8) * 2;
    const int b_n = nb + (lane & 7) + ((lane >> 4) & 1) * 8;
    const int b_k = ((lane >> 3) & 1) * 8;
    const uint32_t boff1 = (uint32_t)b_n * 400 + (uint32_t)b_k * 2;
    const uint32_t boff2 = (uint32_t)b_n * 272 + (uint32_t)b_k * 2;

    const int q = lane >> 2;
    const int cpair = (lane & 3) * 2;
    const float4* colt = (const float4*)(smem + COLT_OFF);

    // ---- prefetch first tile ----
    float4 pv[6];
    if (blockIdx.x < ntiles)
        ld_tile6(src, edg, blockIdx.x * TILE_M, nrows, tid, pv);

    for (int tile = blockIdx.x; tile < ntiles; tile += gridDim.x) {
        const int tbase = tile * TILE_M;

        // ---- stage x tile from prefetched regs: fp32 -> bf16 hi/lo ----
        #pragma unroll
        for (int it = 0; it < 6; ++it) {
            int c   = it * THREADS + tid;
            int row = c / 48;
            int kg  = c - row * 48;
            float4 v = pv[it];
            uint32_t h01 = pack_bf16x2(v.x, v.y);
            uint32_t h23 = pack_bf16x2(v.z, v.w);
            float r0 = v.x - __uint_as_float(h01 << 16);
            float r1 = v.y - __uint_as_float(h01 & 0xffff0000u);
            float r2 = v.z - __uint_as_float(h23 << 16);
            float r3 = v.w - __uint_as_float(h23 & 0xffff0000u);
            uint32_t l01 = pack_bf16x2(r0, r1);
            uint32_t l23 = pack_bf16x2(r2, r3);
            *(uint64_t*)(smem + XSH_OFF + row * 400 + kg * 8) = ((uint64_t)h23 << 32) | h01;
            *(uint64_t*)(smem + XSL_OFF + row * 400 + kg * 8) = ((uint64_t)l23 << 32) | l01;
        }
        __syncthreads();

        // ---- GEMM1: K=192, bf16x3 split (hi*hi + lo*hi + hi*lo) ----
        float acc[4][4];
        #pragma unroll
        for (int f = 0; f < 4; ++f)
            #pragma unroll
            for (int u = 0; u < 4; ++u) acc[f][u] = 0.f;

        #pragma unroll
        for (int s = 0; s < 12; ++s) {
            const uint32_t so = s * 32;
            uint32_t ah[4], al[4], bh[8], bl[8];
            ldsm_x4(ah, sb + XSH_OFF + aoff + so);
            ldsm_x4(al, sb + XSL_OFF + aoff + so);
            ldsm_x4(bh,     sb + W1H_OFF + boff1 + so);
            ldsm_x4(bh + 4, sb + W1H_OFF + boff1 + 6400 + so);
            ldsm_x4(bl,     sb + W1L_OFF + boff1 + so);
            ldsm_x4(bl + 4, sb + W1L_OFF + boff1 + 6400 + so);
            #pragma unroll
            for (int f = 0; f < 4; ++f) mma_bf16(acc[f], ah, &bh[2 * f]);
            #pragma unroll
            for (int f = 0; f < 4; ++f) mma_bf16(acc[f], al, &bh[2 * f]);
            #pragma unroll
            for (int f = 0; f < 4; ++f) mma_bf16(acc[f], ah, &bl[2 * f]);
        }

        // ---- epilogue1: +b1, LN partials (quad shfl + plain STS slots) ----
        #pragma unroll
        for (int h = 0; h < 2; ++h) {
            float s = 0.f, ss = 0.f;
            #pragma unroll
            for (int f = 0; f < 4; ++f) {
                int col = nb + f * 8 + cpair;
                float h0 = acc[f][2 * h]     + colt[col].x;
                float h1 = acc[f][2 * h + 1] + colt[col + 1].x;
                acc[f][2 * h] = h0; acc[f][2 * h + 1] = h1;
                s += h0 + h1;  ss += h0 * h0 + h1 * h1;
            }
            s  += __shfl_xor_sync(0xffffffffu, s, 1);
            s  += __shfl_xor_sync(0xffffffffu, s, 2);
            ss += __shfl_xor_sync(0xffffffffu, ss, 1);
            ss += __shfl_xor_sync(0xffffffffu, ss, 2);
            if ((lane & 3) == 0) {
                int row = rb + h * 8 + q;
                *(float2*)(smem + PSUM_OFF + (row * 4 + cg) * 8) = make_float2(s, ss);
            }
        }
        __syncthreads();

        // ---- LN + SiLU + split -> restage into xs arrays (as h tile) ----
        #pragma unroll
        for (int h = 0; h < 2; ++h) {
            int row = rb + h * 8 + q;
            float4 p01 = *(const float4*)(smem + PSUM_OFF + row * 32);
            float4 p23 = *(const float4*)(smem + PSUM_OFF + row * 32 + 16);
            float s  = p01.x + p01.z + p23.x + p23.z;
            float ss = p01.y + p01.w + p23.y + p23.w;
            float mu  = s * (1.0f / 128.0f);
            float inv = rsqrtf(ss * (1.0f / 128.0f) - mu * mu + 1e-5f);
            #pragma unroll
            for (int f = 0; f < 4; ++f) {
                int col = nb + f * 8 + cpair;
                float4 cA = colt[col], cB = colt[col + 1];
                float g0 = (acc[f][2 * h]     - mu) * inv * cA.y + cA.z;
                float g1 = (acc[f][2 * h + 1] - mu) * inv * cB.y + cB.z;
                float a0 = silu_f(g0), a1 = silu_f(g1);
                uint32_t hw = pack_bf16x2(a0, a1);
                float r0 = a0 - __uint_as_float(hw << 16);
                float r1 = a1 - __uint_as_float(hw & 0xffff0000u);
                uint32_t lw = pack_bf16x2(r0, r1);
                *(uint32_t*)(smem + XSH_OFF + row * 400 + col * 2) = hw;
                *(uint32_t*)(smem + XSL_OFF + row * 400 + col * 2) = lw;
            }
        }
        __syncthreads();

        // ---- GEMM2: K=128 ----
        float ac2[4][4];
        #pragma unroll
        for (int f = 0; f < 4; ++f)
            #pragma unroll
            for (int u = 0; u < 4; ++u) ac2[f][u] = 0.f;

        #pragma unroll
        for (int s = 0; s < 8; ++s) {
            const uint32_t so = s * 32;
            uint32_t ah[4], al[4], bh[8], bl[8];
            ldsm_x4(ah, sb + XSH_OFF + aoff + so);
            ldsm_x4(al, sb + XSL_OFF + aoff + so);
            ldsm_x4(bh,     sb + W2H_OFF + boff2 + so);
            ldsm_x4(bh + 4, sb + W2H_OFF + boff2 + 4352 + so);
            ldsm_x4(bl,     sb + W2L_OFF + boff2 + so);
            ldsm_x4(bl + 4, sb + W2L_OFF + boff2 + 4352 + so);
            #pragma unroll
            for (int f = 0; f < 4; ++f) mma_bf16(ac2[f], ah, &bh[2 * f]);
            #pragma unroll
            for (int f = 0; f < 4; ++f) mma_bf16(ac2[f], al, &bh[2 * f]);
            #pragma unroll
            for (int f = 0; f < 4; ++f) mma_bf16(ac2[f], ah, &bl[2 * f]);
        }

        // ---- prefetch next tile's x (LDG latency hidden behind epilogue2) ----
        {
            int nt = tile + gridDim.x;
            if (nt < ntiles)
                ld_tile6(src, edg, nt * TILE_M, nrows, tid, pv);
        }

        // ---- epilogue2: +b2, SiLU, store ----
        #pragma unroll
        for (int h = 0; h < 2; ++h) {
            int row = rb + h * 8 + q;
            int grow = tbase + row;
            if (grow < nrows) {
                #pragma unroll
                for (int f = 0; f < 4; ++f) {
                    int col = nb + f * 8 + cpair;
                    float o0 = silu_f(ac2[f][2 * h]     + colt[col].w);
                    float o1 = silu_f(ac2[f][2 * h + 1] + colt[col + 1].w);
                    *(float2*)(out + (size_t)grow * NN + col) = make_float2(o0, o1);
                }
            }
        }
        __syncthreads();   // protect xs/psum overwrite vs next tile
    }
}

extern "C" void kernel_launch(void* const* d_in, const int* in_sizes, int n_in,
                              void* d_out, int out_size)
{
    const float* src = (const float*)d_in[0];
    const float* edg = (const float*)d_in[1];
    const float* W1  = (const float*)d_in[2];
    const float* b1  = (const float*)d_in[3];
    const float* gm  = (const float*)d_in[4];
    const float* be  = (const float*)d_in[5];
    const float* W2  = (const float*)d_in[6];
    const float* b2  = (const float*)d_in[7];
    float* out = (float*)d_out;

    const int nrows  = in_sizes[0] / NODE_DIM;
    const int ntiles = (nrows + TILE_M - 1) / TILE_M;

    cudaFuncSetAttribute(edge_mlp_hmma_kernel,
                         cudaFuncAttributeMaxDynamicSharedMemorySize, SMEM_BYTES);

    int dev = 0, sms = 148;
    cudaGetDevice(&dev);
    cudaDeviceGetAttribute(&sms, cudaDevAttrMultiProcessorCount, dev);
    int grid = (sms < ntiles) ? sms : ntiles;

    edge_mlp_hmma_kernel<<<grid, THREADS, SMEM_BYTES>>>(
        src, edg, W1, b1, gm, be, W2, b2, out, nrows, ntiles);
}

// round 15
// speedup vs baseline: 3.9520x; 1.3328x over previous
#include <cuda_runtime.h>
#include <cuda_fp16.h>
#include <cstdint>

#define THREADS  512
#define TILE_M   64
#define NODE_DIM 128
#define EDGE_DIM 64
#define K1       192
#define K2       128
#define NN       128

// ---- SMEM byte offsets (row strides 400B / 272B: stride%128==16 -> conflict-free ldmatrix) ----
#define W1_OFF    0                         // 128*400 = 51200 (fp16 single)
#define W2_OFF    51200                     // 128*272 = 34816 (fp16 single)
#define XSH_OFF   86016                     // 64*400 = 25600 (x/h hi fp16)
#define XSL_OFF   111616                    // 64*400 = 25600 (x/h lo fp16)
#define COLT_OFF  137216                    // float4[128] = 2048
#define PSUM_OFF  139264                    // float2[64][4] = 2048
#define SMEM_BYTES 141312

// ============ PTX helpers (mma.sync path — legal on compute_103) ============
__device__ __forceinline__ uint32_t smem_u32(const void* p) {
    uint32_t a;
    asm("{ .reg .u64 t; cvta.to.shared.u64 t, %1; cvt.u32.u64 %0, t; }" : "=r"(a) : "l"(p));
    return a;
}
__device__ __forceinline__ void ldsm_x4(uint32_t* r, uint32_t addr) {
    asm volatile("ldmatrix.sync.aligned.m8n8.x4.shared.b16 {%0,%1,%2,%3}, [%4];"
        : "=r"(r[0]), "=r"(r[1]), "=r"(r[2]), "=r"(r[3]) : "r"(addr));
}
__device__ __forceinline__ void mma_f16(float* d, const uint32_t* a, const uint32_t* b) {
    asm volatile("mma.sync.aligned.m16n8k16.row.col.f32.f16.f16.f32 "
        "{%0,%1,%2,%3}, {%4,%5,%6,%7}, {%8,%9}, {%0,%1,%2,%3};"
        : "+f"(d[0]), "+f"(d[1]), "+f"(d[2]), "+f"(d[3])
        : "r"(a[0]), "r"(a[1]), "r"(a[2]), "r"(a[3]), "r"(b[0]), "r"(b[1]));
}
// packed f16x2: low half = e0 (first element), high half = e1
__device__ __forceinline__ uint32_t pack_f16x2(float e0, float e1) {
    uint32_t r;
    asm("cvt.rn.f16x2.f32 %0, %1, %2;" : "=r"(r) : "f"(e1), "f"(e0));
    return r;
}
__device__ __forceinline__ uint16_t f16_bits(float x) {
    uint16_t u;
    asm("cvt.rn.f16.f32 %0, %1;" : "=h"(u) : "f"(x));
    return u;
}
// unpack f16x2 -> (lo, hi) as fp32
__device__ __forceinline__ float2 unpack_f16x2(uint32_t w) {
    float lo, hi;
    asm("{ .reg .b16 l,h; mov.b32 {l,h}, %2; cvt.f32.f16 %0, l; cvt.f32.f16 %1, h; }"
        : "=f"(lo), "=f"(hi) : "r"(w));
    return make_float2(lo, hi);
}
// silu(x) = 0.5*x*(1 + tanh(x/2)) — 1 MUFU
__device__ __forceinline__ float silu_f(float x) {
    float t;
    asm("tanh.approx.f32 %0, %1;" : "=f"(t) : "f"(x * 0.5f));
    return 0.5f * x * (1.0f + t);
}

// prefetch one x-tile (64 x 192 fp32) into 6 float4 regs per thread
__device__ __forceinline__ void ld_tile6(const float* __restrict__ src,
                                         const float* __restrict__ edg,
                                         int tbase, int nrows, int tid, float4* pv) {
    #pragma unroll
    for (int it = 0; it < 6; ++it) {
        int c   = it * THREADS + tid;
        int row = c / 48;
        int kg  = c - row * 48;
        int rl  = tbase + row; if (rl >= nrows) rl = nrows - 1;
        pv[it] = (kg < 32)
            ? ((const float4*)(src + (size_t)rl * NODE_DIM))[kg]
            : ((const float4*)(edg + (size_t)rl * EDGE_DIM))[kg - 32];
    }
}

__global__ __launch_bounds__(THREADS, 1)
void edge_mlp_hmma_kernel(const float* __restrict__ src,
                          const float* __restrict__ edg,
                          const float* __restrict__ W1,
                          const float* __restrict__ b1,
                          const float* __restrict__ gamma,
                          const float* __restrict__ beta,
                          const float* __restrict__ W2,
                          const float* __restrict__ b2,
                          float* __restrict__ out,
                          int nrows, int ntiles)
{
    extern __shared__ char smem[];
    const uint32_t sb = smem_u32(smem);
    const int tid  = threadIdx.x;
    const int lane = tid & 31;
    const int wid  = tid >> 5;
    const int rg = wid >> 2;            // rowgroup 0..3 -> rows [rg*16, rg*16+16)
    const int cg = wid & 3;             // colgroup 0..3 -> cols [cg*32, cg*32+32)
    const int rb = rg * 16;
    const int nb = cg * 32;

    // ---- one-time: weights fp32 [k][n] -> fp16 transposed [n][k] ----
    for (int i = tid; i < K1 * NN; i += THREADS) {
        int k = i >> 7, n = i & 127;
        *(uint16_t*)(smem + W1_OFF + n * 400 + k * 2) = f16_bits(W1[i]);
    }
    for (int i = tid; i < K2 * NN; i += THREADS) {
        int k = i >> 7, n = i & 127;
        *(uint16_t*)(smem + W2_OFF + n * 272 + k * 2) = f16_bits(W2[i]);
    }
    if (tid < NN)
        ((float4*)(smem + COLT_OFF))[tid] =
            make_float4(b1[tid], gamma[tid], beta[tid], b2[tid]);
    __syncthreads();

    // ---- per-thread fragment byte offsets ----
    const uint32_t aoff = (uint32_t)(rb + (lane & 15)) * 400 + (uint32_t)((lane >> 4) * 8) * 2;
    const int b_n = nb + (lane & 7) + ((lane >> 4) & 1) * 8;
    const int b_k = ((lane >> 3) & 1) * 8;
    const uint32_t boff1 = (uint32_t)b_n * 400 + (uint32_t)b_k * 2;
    const uint32_t boff2 = (uint32_t)b_n * 272 + (uint32_t)b_k * 2;

    const int q = lane >> 2;
    const int cpair = (lane & 3) * 2;
    const float4* colt = (const float4*)(smem + COLT_OFF);

    // ---- prefetch first tile ----
    float4 pv[6];
    if (blockIdx.x < ntiles)
        ld_tile6(src, edg, blockIdx.x * TILE_M, nrows, tid, pv);

    for (int tile = blockIdx.x; tile < ntiles; tile += gridDim.x) {
        const int tbase = tile * TILE_M;

        // ---- stage x tile from prefetched regs: fp32 -> fp16 hi + fp16 residual ----
        #pragma unroll
        for (int it = 0; it < 6; ++it) {
            int c   = it * THREADS + tid;
            int row = c / 48;
            int kg  = c - row * 48;
            float4 v = pv[it];
            uint32_t h01 = pack_f16x2(v.x, v.y);
            uint32_t h23 = pack_f16x2(v.z, v.w);
            float2 f01 = unpack_f16x2(h01);
            float2 f23 = unpack_f16x2(h23);
            uint32_t l01 = pack_f16x2(v.x - f01.x, v.y - f01.y);
            uint32_t l23 = pack_f16x2(v.z - f23.x, v.w - f23.y);
            *(uint64_t*)(smem + XSH_OFF + row * 400 + kg * 8) = ((uint64_t)h23 << 32) | h01;
            *(uint64_t*)(smem + XSL_OFF + row * 400 + kg * 8) = ((uint64_t)l23 << 32) | l01;
        }
        __syncthreads();

        // ---- GEMM1: K=192, fp16 2-term (x_hi*W + x_lo*W) ----
        float acc[4][4];
        #pragma unroll
        for (int f = 0; f < 4; ++f)
            #pragma unroll
            for (int u = 0; u < 4; ++u) acc[f][u] = 0.f;

        #pragma unroll
        for (int s = 0; s < 12; ++s) {
            const uint32_t so = s * 32;
            uint32_t ah[4], al[4], bw[8];
            ldsm_x4(ah, sb + XSH_OFF + aoff + so);
            ldsm_x4(al, sb + XSL_OFF + aoff + so);
            ldsm_x4(bw,     sb + W1_OFF + boff1 + so);
            ldsm_x4(bw + 4, sb + W1_OFF + boff1 + 6400 + so);
            #pragma unroll
            for (int f = 0; f < 4; ++f) mma_f16(acc[f], ah, &bw[2 * f]);
            #pragma unroll
            for (int f = 0; f < 4; ++f) mma_f16(acc[f], al, &bw[2 * f]);
        }

        // ---- epilogue1: +b1, LN partials (quad shfl + plain STS slots) ----
        #pragma unroll
        for (int h = 0; h < 2; ++h) {
            float s = 0.f, ss = 0.f;
            #pragma unroll
            for (int f = 0; f < 4; ++f) {
                int col = nb + f * 8 + cpair;
                float h0 = acc[f][2 * h]     + colt[col].x;
                float h1 = acc[f][2 * h + 1] + colt[col + 1].x;
                acc[f][2 * h] = h0; acc[f][2 * h + 1] = h1;
                s += h0 + h1;  ss += h0 * h0 + h1 * h1;
            }
            s  += __shfl_xor_sync(0xffffffffu, s, 1);
            s  += __shfl_xor_sync(0xffffffffu, s, 2);
            ss += __shfl_xor_sync(0xffffffffu, ss, 1);
            ss += __shfl_xor_sync(0xffffffffu, ss, 2);
            if ((lane & 3) == 0) {
                int row = rb + h * 8 + q;
                *(float2*)(smem + PSUM_OFF + (row * 4 + cg) * 8) = make_float2(s, ss);
            }
        }
        __syncthreads();

        // ---- LN + SiLU + fp16 split -> restage into xs arrays (as h tile) ----
        #pragma unroll
        for (int h = 0; h < 2; ++h) {
            int row = rb + h * 8 + q;
            float4 p01 = *(const float4*)(smem + PSUM_OFF + row * 32);
            float4 p23 = *(const float4*)(smem + PSUM_OFF + row * 32 + 16);
            float s  = p01.x + p01.z + p23.x + p23.z;
            float ss = p01.y + p01.w + p23.y + p23.w;
            float mu  = s * (1.0f / 128.0f);
            float inv = rsqrtf(ss * (1.0f / 128.0f) - mu * mu + 1e-5f);
            #pragma unroll
            for (int f = 0; f < 4; ++f) {
                int col = nb + f * 8 + cpair;
                float4 cA = colt[col], cB = colt[col + 1];
                float g0 = (acc[f][2 * h]     - mu) * inv * cA.y + cA.z;
                float g1 = (acc[f][2 * h + 1] - mu) * inv * cB.y + cB.z;
                float a0 = silu_f(g0), a1 = silu_f(g1);
                uint32_t hw = pack_f16x2(a0, a1);
                float2 fh = unpack_f16x2(hw);
                uint32_t lw = pack_f16x2(a0 - fh.x, a1 - fh.y);
                *(uint32_t*)(smem + XSH_OFF + row * 400 + col * 2) = hw;
                *(uint32_t*)(smem + XSL_OFF + row * 400 + col * 2) = lw;
            }
        }
        __syncthreads();

        // ---- GEMM2: K=128, fp16 2-term ----
        float ac2[4][4];
        #pragma unroll
        for (int f = 0; f < 4; ++f)
            #pragma unroll
            for (int u = 0; u < 4; ++u) ac2[f][u] = 0.f;

        #pragma unroll
        for (int s = 0; s < 8; ++s) {
            const uint32_t so = s * 32;
            uint32_t ah[4], al[4], bw[8];
            ldsm_x4(ah, sb + XSH_OFF + aoff + so);
            ldsm_x4(al, sb + XSL_OFF + aoff + so);
            ldsm_x4(bw,     sb + W2_OFF + boff2 + so);
            ldsm_x4(bw + 4, sb + W2_OFF + boff2 + 4352 + so);
            #pragma unroll
            for (int f = 0; f < 4; ++f) mma_f16(ac2[f], ah, &bw[2 * f]);
            #pragma unroll
            for (int f = 0; f < 4; ++f) mma_f16(ac2[f], al, &bw[2 * f]);
        }

        // ---- prefetch next tile's x (LDG latency hidden behind epilogue2) ----
        {
            int nt = tile + gridDim.x;
            if (nt < ntiles)
                ld_tile6(src, edg, nt * TILE_M, nrows, tid, pv);
        }

        // ---- epilogue2: +b2, SiLU, store ----
        #pragma unroll
        for (int h = 0; h < 2; ++h) {
            int row = rb + h * 8 + q;
            int grow = tbase + row;
            if (grow < nrows) {
                #pragma unroll
                for (int f = 0; f < 4; ++f) {
                    int col = nb + f * 8 + cpair;
                    float o0 = silu_f(ac2[f][2 * h]     + colt[col].w);
                    float o1 = silu_f(ac2[f][2 * h + 1] + colt[col + 1].w);
                    *(float2*)(out + (size_t)grow * NN + col) = make_float2(o0, o1);
                }
            }
        }
        __syncthreads();   // protect xs/psum overwrite vs next tile
    }
}

extern "C" void kernel_launch(void* const* d_in, const int* in_sizes, int n_in,
                              void* d_out, int out_size)
{
    const float* src = (const float*)d_in[0];
    const float* edg = (const float*)d_in[1];
    const float* W1  = (const float*)d_in[2];
    const float* b1  = (const float*)d_in[3];
    const float* gm  = (const float*)d_in[4];
    const float* be  = (const float*)d_in[5];
    const float* W2  = (const float*)d_in[6];
    const float* b2  = (const float*)d_in[7];
    float* out = (float*)d_out;

    const int nrows  = in_sizes[0] / NODE_DIM;
    const int ntiles = (nrows + TILE_M - 1) / TILE_M;

    cudaFuncSetAttribute(edge_mlp_hmma_kernel,
                         cudaFuncAttributeMaxDynamicSharedMemorySize, SMEM_BYTES);

    int dev = 0, sms = 148;
    cudaGetDevice(&dev);
    cudaDeviceGetAttribute(&sms, cudaDevAttrMultiProcessorCount, dev);
    int grid = (sms < ntiles) ? sms : ntiles;

    edge_mlp_hmma_kernel<<<grid, THREADS, SMEM_BYTES>>>(
        src, edg, W1, b1, gm, be, W2, b2, out, nrows, ntiles);
}